// round 14
// baseline (speedup 1.0000x reference)
#include <cuda_runtime.h>
#include <cuda_fp16.h>
#include <cstdint>

// ============================================================================
// treelstm: c = i*u + sum_n sigmoid(child_h @ W_fh^T + b_fh) * child_c
//           h = o * tanh(c)
// R11 (resubmit; R12 was an infra failure, kernel never ran):
// A (child_h) loaded as fp32 via cp.async, converted to fp16 in-register
// during fragment construction (LDS.64 + cvt) -> child_h pre-convert pass
// eliminated (~14 us). B (W_fh) still pre-converted fp16 (tiny). Persistent
// 148-CTA fgemm, continuous 4-stage cp.async pipeline, f32-acc HMMA.
// ============================================================================

#define MEM_DIM 1024
#define N_CHILD 16384
#define NUM_CTAS 148
#define NUM_TILES 1024          // 128 row tiles x 8 col tiles

// Scratch (device globals — no allocation allowed)
__device__ float d_scr[1024 * 128];                       // [col][rowtile]
__device__ __align__(16) __half d_w16[MEM_DIM * MEM_DIM]; // fp16 W_fh

// ---------------- helpers ----------------
__device__ __forceinline__ uint32_t smem_u32(const void* p) {
    uint32_t a;
    asm("{ .reg .u64 t; cvta.to.shared.u64 t, %1; cvt.u32.u64 %0, t; }"
        : "=r"(a) : "l"(p));
    return a;
}
__device__ __forceinline__ void ldmx4(uint32_t& r0, uint32_t& r1,
                                      uint32_t& r2, uint32_t& r3, uint32_t a) {
    asm volatile("ldmatrix.sync.aligned.m8n8.x4.shared.b16 {%0,%1,%2,%3}, [%4];"
                 : "=r"(r0), "=r"(r1), "=r"(r2), "=r"(r3) : "r"(a));
}
__device__ __forceinline__ float2 lds_f2(uint32_t a) {
    float2 v;
    asm volatile("ld.shared.v2.f32 {%0,%1}, [%2];"
                 : "=f"(v.x), "=f"(v.y) : "r"(a));
    return v;
}
__device__ __forceinline__ uint32_t pack_h2(float2 v) {
    __half2 h = __floats2half2_rn(v.x, v.y);
    return *reinterpret_cast<uint32_t*>(&h);
}
__device__ __forceinline__ void mma16816(float* c, const uint32_t* a,
                                         uint32_t b0, uint32_t b1) {
    asm volatile(
        "mma.sync.aligned.m16n8k16.row.col.f32.f16.f16.f32 "
        "{%0,%1,%2,%3}, {%4,%5,%6,%7}, {%8,%9}, {%0,%1,%2,%3};"
        : "+f"(c[0]), "+f"(c[1]), "+f"(c[2]), "+f"(c[3])
        : "r"(a[0]), "r"(a[1]), "r"(a[2]), "r"(a[3]), "r"(b0), "r"(b1));
}
__device__ __forceinline__ float sigmoidf_(float x) {
    return 1.0f / (1.0f + __expf(-x));
}
#define CP_ASYNC16(dst, src) \
    asm volatile("cp.async.cg.shared.global [%0], [%1], 16;" \
                 :: "r"(dst), "l"(src) : "memory")
#define CP_COMMIT() asm volatile("cp.async.commit_group;" ::: "memory")
#define CP_WAIT(n)  asm volatile("cp.async.wait_group %0;" :: "n"(n) : "memory")

// ---------------- kernel 0: fp32 -> fp16 convert (W_fh only) ----------------
__global__ void __launch_bounds__(256)
cvt_kernel(const float* __restrict__ W_fh) {
    size_t i = (size_t)blockIdx.x * 256 + threadIdx.x;   // 8 elems each
    const float4* s4 = reinterpret_cast<const float4*>(W_fh) + i * 2;
    float4 v0 = s4[0], v1 = s4[1];
    __half2 p0 = __floats2half2_rn(v0.x, v0.y);
    __half2 p1 = __floats2half2_rn(v0.z, v0.w);
    __half2 p2 = __floats2half2_rn(v1.x, v1.y);
    __half2 p3 = __floats2half2_rn(v1.z, v1.w);
    uint4 u;
    u.x = *reinterpret_cast<uint32_t*>(&p0);
    u.y = *reinterpret_cast<uint32_t*>(&p1);
    u.z = *reinterpret_cast<uint32_t*>(&p2);
    u.w = *reinterpret_cast<uint32_t*>(&p3);
    reinterpret_cast<uint4*>(d_w16)[i] = u;
}

// ---------------- kernel 1: persistent pipelined f-GEMM + colsum ----------------
// 148 CTAs x 512 threads (16 warps: 4m x 4n). Tile 128x128, warp tile 32x32,
// BK=64. Stage: A fp32 32KB (128 rows x 256B, 16 chunks, sw = ck^((r&7)<<1)),
//              B fp16 16KB (128 rows x 128B, 8 chunks, sw = ck^(r&7)).
static constexpr int STAGE_BYTES = 49152;
static constexpr int OFF_B = 32768;              // within stage
static constexpr int OFF_CSM = 196608;           // 512 floats
static constexpr int SMEM_BYTES = 198656;

__global__ void __launch_bounds__(512, 1)
fgemm_kernel(const float* __restrict__ child_h, const float* __restrict__ child_c,
             const float* __restrict__ b_fh) {
    extern __shared__ char smem[];
    const uint32_t sb = smem_u32(smem);
    const int tid = threadIdx.x;
    const int lid = tid & 31, wid = tid >> 5;
    const int wm = wid & 3, wn = wid >> 2;       // 4 m-warps x 4 n-warps
    const int cta = blockIdx.x;

    int nt = 0;
    for (int t = cta; t < NUM_TILES; t += NUM_CTAS) nt++;
    const int total_chunks = nt * 16;

    // cp.async slots: A 4 x 16B (fp32), B 2 x 16B (fp16) per thread per stage
    const int rL = tid >> 2;
    const int ckA = (tid & 3) * 4;               // 4 of 16 fp32 chunks
    const int ckB = (tid & 3) * 2;               // 2 of 8 fp16 chunks
    uint32_t dA[4], dB[2];
    #pragma unroll
    for (int j = 0; j < 4; j++)
        dA[j] = sb + rL * 256 + (uint32_t)(((ckA + j) ^ ((rL & 7) << 1)) << 4);
    #pragma unroll
    for (int j = 0; j < 2; j++)
        dB[j] = sb + OFF_B + rL * 128 + (uint32_t)(((ckB + j) ^ (rL & 7)) << 4);

    #define ISSUE(l) do { \
        if ((l) < total_chunks) { \
            int t_ = cta + ((l) >> 4) * NUM_CTAS; \
            int kc_ = (l) & 15; \
            uint32_t so = (uint32_t)(((l) & 3) * STAGE_BYTES); \
            const float* ga = child_h + \
                (size_t)(((t_ >> 3) * 128) + rL) * 1024 + kc_ * 64 + ckA * 4; \
            const __half* gb = d_w16 + \
                (size_t)(((t_ & 7) * 128) + rL) * 1024 + kc_ * 64 + ckB * 8; \
            CP_ASYNC16(dA[0] + so, ga); \
            CP_ASYNC16(dA[1] + so, ga + 4); \
            CP_ASYNC16(dA[2] + so, ga + 8); \
            CP_ASYNC16(dA[3] + so, ga + 12); \
            CP_ASYNC16(dB[0] + so, gb); \
            CP_ASYNC16(dB[1] + so, gb + 8); \
        } \
        CP_COMMIT(); \
    } while (0)

    ISSUE(0); ISSUE(1); ISSUE(2);

    // A-fragment LDS addressing: lane = arow*4 + tg needs
    // (arow, 2tg), (arow+8, 2tg), (arow, 2tg+8), (arow+8, 2tg+8)
    // fp32 chunk = ks*4 + (tg>>1), byte-in-chunk = (tg&1)*8, +8 cols = +2 chunks
    const int arow = lid >> 2;                   // 0..7 within 16-row frag
    const int asub = (lid & 3) & 1;              // 8B offset within chunk
    const int ack0 = (lid & 3) >> 1;             // chunk sub-index from lane

    float acc[2][4][4];
    for (int ti = 0; ti < nt; ti++) {
        const int t = cta + ti * NUM_CTAS;
        const int rowBase = (t >> 3) * 128;
        const int colBase = (t & 7) * 128;

        #pragma unroll
        for (int mf = 0; mf < 2; mf++)
            #pragma unroll
            for (int nf = 0; nf < 4; nf++)
                #pragma unroll
                for (int v = 0; v < 4; v++) acc[mf][nf][v] = 0.f;

        for (int kc = 0; kc < 16; kc++) {
            CP_WAIT(2);
            __syncthreads();
            ISSUE(ti * 16 + kc + 3);

            const uint32_t au = sb + (kc & 3) * STAGE_BYTES;
            const uint32_t bu = au + OFF_B;
            #pragma unroll
            for (int ks = 0; ks < 4; ks++) {
                uint32_t a[2][4], b[2][4];
                // A fragments: fp32 LDS pairs -> half2
                #pragma unroll
                for (int mf = 0; mf < 2; mf++) {
                    const int r = wm * 32 + mf * 16 + arow;
                    const int sw = (r & 7) << 1;
                    const int ck = ks * 4 + ack0;
                    const uint32_t base = au + r * 256 + asub * 8;
                    const uint32_t a0 = base + (uint32_t)((ck ^ sw) << 4);
                    const uint32_t a2 = base + (uint32_t)(((ck + 2) ^ sw) << 4);
                    a[mf][0] = pack_h2(lds_f2(a0));
                    a[mf][1] = pack_h2(lds_f2(a0 + 2048));
                    a[mf][2] = pack_h2(lds_f2(a2));
                    a[mf][3] = pack_h2(lds_f2(a2 + 2048));
                }
                // B fragments: fp16 ldmatrix
                const int chunk = ks * 2 + (lid >> 4);
                #pragma unroll
                for (int nh = 0; nh < 2; nh++) {
                    int r = wn * 32 + nh * 16 + (lid & 15);
                    ldmx4(b[nh][0], b[nh][1], b[nh][2], b[nh][3],
                          bu + r * 128 + ((chunk ^ (r & 7)) << 4));
                }
                #pragma unroll
                for (int mf = 0; mf < 2; mf++)
                    #pragma unroll
                    for (int nf = 0; nf < 4; nf++)
                        mma16816(acc[mf][nf], a[mf],
                                 b[nf >> 1][nf & 1], b[nf >> 1][(nf & 1) + 2]);
            }
        }
        __syncthreads();   // next tile's stages already in flight

        // ---- epilogue: f = sigmoid(z + b); colsum over rows of f*child_c ----
        const int g = lid >> 2, tg = lid & 3;
        float cs0[4], cs1[4];
        #pragma unroll
        for (int nf = 0; nf < 4; nf++) {
            const int c0 = colBase + wn * 32 + nf * 8 + tg * 2;
            const float b0 = __ldg(b_fh + c0), b1 = __ldg(b_fh + c0 + 1);
            float s0 = 0.f, s1 = 0.f;
            #pragma unroll
            for (int mf = 0; mf < 2; mf++) {
                const int r0 = rowBase + wm * 32 + mf * 16 + g;
                const float* cc = child_c + (size_t)r0 * 1024 + c0;
                float2 cA = *reinterpret_cast<const float2*>(cc);
                float2 cB = *reinterpret_cast<const float2*>(cc + 8 * 1024);
                s0 += sigmoidf_(acc[mf][nf][0] + b0) * cA.x;
                s1 += sigmoidf_(acc[mf][nf][1] + b1) * cA.y;
                s0 += sigmoidf_(acc[mf][nf][2] + b0) * cB.x;
                s1 += sigmoidf_(acc[mf][nf][3] + b1) * cB.y;
            }
            #pragma unroll
            for (int off = 4; off <= 16; off <<= 1) {
                s0 += __shfl_xor_sync(0xffffffffu, s0, off);
                s1 += __shfl_xor_sync(0xffffffffu, s1, off);
            }
            cs0[nf] = s0;
            cs1[nf] = s1;
        }
        float* csm = reinterpret_cast<float*>(smem + OFF_CSM);
        if (g == 0) {
            #pragma unroll
            for (int nf = 0; nf < 4; nf++) {
                csm[wm * 128 + wn * 32 + nf * 8 + tg * 2] = cs0[nf];
                csm[wm * 128 + wn * 32 + nf * 8 + tg * 2 + 1] = cs1[nf];
            }
        }
        __syncthreads();
        if (tid < 128)
            d_scr[(size_t)(colBase + tid) * 128 + (t >> 3)] =
                csm[tid] + csm[128 + tid] + csm[256 + tid] + csm[384 + tid];
        __syncthreads();
    }
}

// ---------------- kernel 2: gates + reduce + combine ----------------
__global__ void __launch_bounds__(128)
final_kernel(float* __restrict__ out, const float* __restrict__ hsum,
             const float* __restrict__ W_ih, const float* __restrict__ b_ih,
             const float* __restrict__ W_uh, const float* __restrict__ b_uh,
             const float* __restrict__ W_oh, const float* __restrict__ b_oh) {
    const int j = blockIdx.x;
    const int tid = threadIdx.x, wid = tid >> 5, lid = tid & 31;
    __shared__ float red[4];

    float s = 0.f;
    if (wid < 3) {
        const float* W = (wid == 0) ? W_ih : ((wid == 1) ? W_uh : W_oh);
        const float4* Wr = reinterpret_cast<const float4*>(W + (size_t)j * 1024);
        const float4* h4 = reinterpret_cast<const float4*>(hsum);
        #pragma unroll
        for (int st = 0; st < 8; st++) {
            float4 w = Wr[lid + st * 32];
            float4 h = h4[lid + st * 32];
            s += w.x * h.x + w.y * h.y + w.z * h.z + w.w * h.w;
        }
    } else {
        float4 v = reinterpret_cast<const float4*>(d_scr + (size_t)j * 128)[lid];
        s = v.x + v.y + v.z + v.w;
    }
    #pragma unroll
    for (int off = 16; off; off >>= 1) s += __shfl_xor_sync(0xffffffffu, s, off);
    if (lid == 0) red[wid] = s;
    __syncthreads();
    if (tid == 0) {
        float i = sigmoidf_(red[0] + b_ih[j]);
        float u = tanhf(red[1] + b_uh[j]);
        float o = sigmoidf_(red[2] + b_oh[j]);
        float c = i * u + red[3];
        out[j] = c;
        out[1024 + j] = o * tanhf(c);
    }
}

// ---------------- launch ----------------
extern "C" void kernel_launch(void* const* d_in, const int* in_sizes, int n_in,
                              void* d_out, int out_size) {
    (void)in_sizes; (void)n_in; (void)out_size;
    const float* child_c = (const float*)d_in[0];
    const float* child_h = (const float*)d_in[1];
    const float* hsum    = (const float*)d_in[2];
    const float* W_ih    = (const float*)d_in[3];
    const float* b_ih    = (const float*)d_in[4];
    const float* W_fh    = (const float*)d_in[5];
    const float* b_fh    = (const float*)d_in[6];
    const float* W_uh    = (const float*)d_in[7];
    const float* b_uh    = (const float*)d_in[8];
    const float* W_oh    = (const float*)d_in[9];
    const float* b_oh    = (const float*)d_in[10];
    float* out = (float*)d_out;

    cudaFuncSetAttribute(fgemm_kernel, cudaFuncAttributeMaxDynamicSharedMemorySize,
                         SMEM_BYTES);

    cvt_kernel<<<512, 256>>>(W_fh);
    fgemm_kernel<<<NUM_CTAS, 512, SMEM_BYTES>>>(child_h, child_c, b_fh);
    final_kernel<<<1024, 128>>>(out, hsum, W_ih, b_ih, W_uh, b_uh, W_oh, b_oh);
}

// round 16
// speedup vs baseline: 1.2421x; 1.2421x over previous
#include <cuda_runtime.h>
#include <cuda_fp16.h>
#include <cstdint>

// ============================================================================
// treelstm: c = i*u + sum_n sigmoid(child_h @ W_fh^T + b_fh) * child_c
//           h = o * tanh(c)
// R15: revert R11 A-fp32 experiment (regressed: LDS+cvt starved tensor pipe).
// R10 core (persistent 148-CTA, fp16 HMMA f32-acc, continuous cp.async) +
//  - 3-stage pipeline (frees 96KB SMEM)
//  - child_c tile prefetched into SMEM via same cp.async stream (epilogue
//    DRAM-latency loads -> LDS)
//  - __ldcs on child_h in cvt (read-once; preserve L2 for d_h16/W/child_c)
// ============================================================================

#define MEM_DIM 1024
#define N_CHILD 16384
#define NUM_CTAS 148
#define NUM_TILES 1024          // 128 row tiles x 8 col tiles

// Scratch (device globals — no allocation allowed)
__device__ float d_scr[1024 * 128];                       // [col][rowtile]
__device__ __align__(16) __half d_h16[N_CHILD * MEM_DIM]; // fp16 child_h
__device__ __align__(16) __half d_w16[MEM_DIM * MEM_DIM]; // fp16 W_fh

// ---------------- helpers ----------------
__device__ __forceinline__ uint32_t smem_u32(const void* p) {
    uint32_t a;
    asm("{ .reg .u64 t; cvta.to.shared.u64 t, %1; cvt.u32.u64 %0, t; }"
        : "=r"(a) : "l"(p));
    return a;
}
__device__ __forceinline__ void ldmx4(uint32_t& r0, uint32_t& r1,
                                      uint32_t& r2, uint32_t& r3, uint32_t a) {
    asm volatile("ldmatrix.sync.aligned.m8n8.x4.shared.b16 {%0,%1,%2,%3}, [%4];"
                 : "=r"(r0), "=r"(r1), "=r"(r2), "=r"(r3) : "r"(a));
}
__device__ __forceinline__ float2 lds_f2(uint32_t a) {
    float2 v;
    asm volatile("ld.shared.v2.f32 {%0,%1}, [%2];"
                 : "=f"(v.x), "=f"(v.y) : "r"(a));
    return v;
}
__device__ __forceinline__ void mma16816(float* c, const uint32_t* a,
                                         uint32_t b0, uint32_t b1) {
    asm volatile(
        "mma.sync.aligned.m16n8k16.row.col.f32.f16.f16.f32 "
        "{%0,%1,%2,%3}, {%4,%5,%6,%7}, {%8,%9}, {%0,%1,%2,%3};"
        : "+f"(c[0]), "+f"(c[1]), "+f"(c[2]), "+f"(c[3])
        : "r"(a[0]), "r"(a[1]), "r"(a[2]), "r"(a[3]), "r"(b0), "r"(b1));
}
__device__ __forceinline__ float sigmoidf_(float x) {
    return 1.0f / (1.0f + __expf(-x));
}
#define CP_ASYNC16(dst, src) \
    asm volatile("cp.async.cg.shared.global [%0], [%1], 16;" \
                 :: "r"(dst), "l"(src) : "memory")
#define CP_COMMIT() asm volatile("cp.async.commit_group;" ::: "memory")
#define CP_WAIT(n)  asm volatile("cp.async.wait_group %0;" :: "n"(n) : "memory")

// ---------------- kernel 0: fp32 -> fp16 convert (both arrays) ----------------
// blocks [0, 8192): child_h; blocks [8192, 8704): W_fh
__global__ void __launch_bounds__(256)
cvt_kernel(const float* __restrict__ child_h, const float* __restrict__ W_fh) {
    const float* src;
    __half* dst;
    size_t i;
    if (blockIdx.x < 8192) {
        src = child_h;
        dst = d_h16;
        i = (size_t)blockIdx.x * 256 + threadIdx.x;
    } else {
        src = W_fh;
        dst = d_w16;
        i = (size_t)(blockIdx.x - 8192) * 256 + threadIdx.x;
    }
    const float4* s4 = reinterpret_cast<const float4*>(src) + i * 2;
    float4 v0 = __ldcs(s4);
    float4 v1 = __ldcs(s4 + 1);
    __half2 p0 = __floats2half2_rn(v0.x, v0.y);
    __half2 p1 = __floats2half2_rn(v0.z, v0.w);
    __half2 p2 = __floats2half2_rn(v1.x, v1.y);
    __half2 p3 = __floats2half2_rn(v1.z, v1.w);
    uint4 u;
    u.x = *reinterpret_cast<uint32_t*>(&p0);
    u.y = *reinterpret_cast<uint32_t*>(&p1);
    u.z = *reinterpret_cast<uint32_t*>(&p2);
    u.w = *reinterpret_cast<uint32_t*>(&p3);
    reinterpret_cast<uint4*>(dst)[i] = u;
}

// ---------------- kernel 1: persistent pipelined f-GEMM + colsum ----------------
// 148 CTAs x 512 threads (16 warps: 4m x 4n). Tile 128x128, warp tile 32x32,
// BK=64, 3-stage cp.async pipeline continuous across tiles + child_c prefetch.
static constexpr int STAGE_BYTES = 32768;        // A 16KB + B 16KB
static constexpr int CC_STRIDE = 528;            // 128 f32 + 16B pad (bank spread)
static constexpr int OFF_CC = 3 * STAGE_BYTES;   // 98304; 128 x 528 = 67584
static constexpr int OFF_CSM = OFF_CC + 128 * CC_STRIDE;   // 165888
static constexpr int SMEM_BYTES = OFF_CSM + 2048;          // 167936

__global__ void __launch_bounds__(512, 1)
fgemm_kernel(const float* __restrict__ child_c, const float* __restrict__ b_fh) {
    extern __shared__ char smem[];
    const uint32_t sb = smem_u32(smem);
    const int tid = threadIdx.x;
    const int lid = tid & 31, wid = tid >> 5;
    const int wm = wid & 3, wn = wid >> 2;       // 4 m-warps x 4 n-warps
    const int cta = blockIdx.x;

    int nt = 0;
    for (int t = cta; t < NUM_TILES; t += NUM_CTAS) nt++;
    const int total_chunks = nt * 16;

    // per-thread load slots: 2 A chunks + 2 B chunks (4 x 16B)
    const int rL = tid >> 2, ckL = (tid & 3) * 2;   // 128 rows, 2 chunks each
    const uint32_t dA0 = sb + rL * 128 + (((ckL) ^ (rL & 7)) << 4);
    const uint32_t dA1 = sb + rL * 128 + (((ckL + 1) ^ (rL & 7)) << 4);
    const uint32_t dB0 = sb + 16384 + rL * 128 + (((ckL) ^ (rL & 7)) << 4);
    const uint32_t dB1 = sb + 16384 + rL * 128 + (((ckL + 1) ^ (rL & 7)) << 4);
    // child_c prefetch: row rL, 8 chunks of 16B per thread, 2 batches of 4
    const uint32_t dC0 = sb + OFF_CC + rL * CC_STRIDE + (tid & 3) * 128;

    // issue global chunk l of this CTA's stream (always commits).
    // chunks with (l&15)==8,9 also prefetch this tile's child_c block.
    #define ISSUE(l) do { \
        if ((l) < total_chunks) { \
            int t_ = cta + ((l) >> 4) * NUM_CTAS; \
            int kc_ = (l) & 15; \
            uint32_t so = (uint32_t)(((l) % 3) * STAGE_BYTES); \
            const __half* ga = d_h16 + \
                (size_t)(((t_ >> 3) * 128) + rL) * 1024 + kc_ * 64 + ckL * 8; \
            const __half* gb = d_w16 + \
                (size_t)(((t_ & 7) * 128) + rL) * 1024 + kc_ * 64 + ckL * 8; \
            CP_ASYNC16(dA0 + so, ga); \
            CP_ASYNC16(dA1 + so, ga + 8); \
            CP_ASYNC16(dB0 + so, gb); \
            CP_ASYNC16(dB1 + so, gb + 8); \
            if (kc_ == 8 || kc_ == 9) { \
                int ph = kc_ - 8; \
                const float* gc = child_c + \
                    (size_t)(((t_ >> 3) * 128) + rL) * 1024 + \
                    ((t_ & 7) * 128) + (tid & 3) * 32 + ph * 16; \
                uint32_t dc = dC0 + (uint32_t)(ph * 64); \
                CP_ASYNC16(dc, gc); \
                CP_ASYNC16(dc + 16, gc + 4); \
                CP_ASYNC16(dc + 32, gc + 8); \
                CP_ASYNC16(dc + 48, gc + 12); \
            } \
        } \
        CP_COMMIT(); \
    } while (0)

    ISSUE(0); ISSUE(1);

    float acc[2][4][4];
    for (int ti = 0; ti < nt; ti++) {
        const int t = cta + ti * NUM_CTAS;
        const int rowBase = (t >> 3) * 128;
        const int colBase = (t & 7) * 128;

        #pragma unroll
        for (int mf = 0; mf < 2; mf++)
            #pragma unroll
            for (int nf = 0; nf < 4; nf++)
                #pragma unroll
                for (int v = 0; v < 4; v++) acc[mf][nf][v] = 0.f;

        for (int kc = 0; kc < 16; kc++) {
            const int gl = ti * 16 + kc;
            CP_WAIT(1);
            __syncthreads();
            ISSUE(gl + 2);

            const uint32_t au = sb + (uint32_t)((gl % 3) * STAGE_BYTES);
            const uint32_t bu = au + 16384;
            #pragma unroll
            for (int ks = 0; ks < 4; ks++) {
                const int chunk = ks * 2 + (lid >> 4);
                uint32_t a[2][4], b[2][4];
                #pragma unroll
                for (int mf = 0; mf < 2; mf++) {
                    int r = wm * 32 + mf * 16 + (lid & 15);
                    ldmx4(a[mf][0], a[mf][1], a[mf][2], a[mf][3],
                          au + r * 128 + ((chunk ^ (r & 7)) << 4));
                }
                #pragma unroll
                for (int nh = 0; nh < 2; nh++) {
                    int r = wn * 32 + nh * 16 + (lid & 15);
                    ldmx4(b[nh][0], b[nh][1], b[nh][2], b[nh][3],
                          bu + r * 128 + ((chunk ^ (r & 7)) << 4));
                }
                #pragma unroll
                for (int mf = 0; mf < 2; mf++)
                    #pragma unroll
                    for (int nf = 0; nf < 4; nf++)
                        mma16816(acc[mf][nf], a[mf],
                                 b[nf >> 1][nf & 1], b[nf >> 1][(nf & 1) + 2]);
            }
        }
        __syncthreads();   // child_c prefetch groups (kc 8,9) drained by the
                           // kc=15 wait; barrier makes them block-visible

        // ---- epilogue: f = sigmoid(z + b); colsum over rows of f*child_c ----
        const int g = lid >> 2, tg = lid & 3;
        float cs0[4], cs1[4];
        #pragma unroll
        for (int nf = 0; nf < 4; nf++) {
            const int c0 = colBase + wn * 32 + nf * 8 + tg * 2;
            const float b0 = __ldg(b_fh + c0), b1 = __ldg(b_fh + c0 + 1);
            const uint32_t ccb = sb + OFF_CC +
                (uint32_t)((wn * 32 + nf * 8 + tg * 2) * 4);
            float s0 = 0.f, s1 = 0.f;
            #pragma unroll
            for (int mf = 0; mf < 2; mf++) {
                const int rl = wm * 32 + mf * 16 + g;
                float2 cA = lds_f2(ccb + rl * CC_STRIDE);
                float2 cB = lds_f2(ccb + (rl + 8) * CC_STRIDE);
                s0 += sigmoidf_(acc[mf][nf][0] + b0) * cA.x;
                s1 += sigmoidf_(acc[mf][nf][1] + b1) * cA.y;
                s0 += sigmoidf_(acc[mf][nf][2] + b0) * cB.x;
                s1 += sigmoidf_(acc[mf][nf][3] + b1) * cB.y;
            }
            #pragma unroll
            for (int off = 4; off <= 16; off <<= 1) {
                s0 += __shfl_xor_sync(0xffffffffu, s0, off);
                s1 += __shfl_xor_sync(0xffffffffu, s1, off);
            }
            cs0[nf] = s0;
            cs1[nf] = s1;
        }
        float* csm = reinterpret_cast<float*>(smem + OFF_CSM);
        if (g == 0) {
            #pragma unroll
            for (int nf = 0; nf < 4; nf++) {
                csm[wm * 128 + wn * 32 + nf * 8 + tg * 2] = cs0[nf];
                csm[wm * 128 + wn * 32 + nf * 8 + tg * 2 + 1] = cs1[nf];
            }
        }
        __syncthreads();
        if (tid < 128)
            d_scr[(size_t)(colBase + tid) * 128 + (t >> 3)] =
                csm[tid] + csm[128 + tid] + csm[256 + tid] + csm[384 + tid];
        __syncthreads();   // protect CSM and child_c buffer before next tile
    }
}

// ---------------- kernel 2: gates + reduce + combine ----------------
__global__ void __launch_bounds__(128)
final_kernel(float* __restrict__ out, const float* __restrict__ hsum,
             const float* __restrict__ W_ih, const float* __restrict__ b_ih,
             const float* __restrict__ W_uh, const float* __restrict__ b_uh,
             const float* __restrict__ W_oh, const float* __restrict__ b_oh) {
    const int j = blockIdx.x;
    const int tid = threadIdx.x, wid = tid >> 5, lid = tid & 31;
    __shared__ float red[4];

    float s = 0.f;
    if (wid < 3) {
        const float* W = (wid == 0) ? W_ih : ((wid == 1) ? W_uh : W_oh);
        const float4* Wr = reinterpret_cast<const float4*>(W + (size_t)j * 1024);
        const float4* h4 = reinterpret_cast<const float4*>(hsum);
        #pragma unroll
        for (int st = 0; st < 8; st++) {
            float4 w = Wr[lid + st * 32];
            float4 h = h4[lid + st * 32];
            s += w.x * h.x + w.y * h.y + w.z * h.z + w.w * h.w;
        }
    } else {
        float4 v = reinterpret_cast<const float4*>(d_scr + (size_t)j * 128)[lid];
        s = v.x + v.y + v.z + v.w;
    }
    #pragma unroll
    for (int off = 16; off; off >>= 1) s += __shfl_xor_sync(0xffffffffu, s, off);
    if (lid == 0) red[wid] = s;
    __syncthreads();
    if (tid == 0) {
        float i = sigmoidf_(red[0] + b_ih[j]);
        float u = tanhf(red[1] + b_uh[j]);
        float o = sigmoidf_(red[2] + b_oh[j]);
        float c = i * u + red[3];
        out[j] = c;
        out[1024 + j] = o * tanhf(c);
    }
}

// ---------------- launch ----------------
extern "C" void kernel_launch(void* const* d_in, const int* in_sizes, int n_in,
                              void* d_out, int out_size) {
    (void)in_sizes; (void)n_in; (void)out_size;
    const float* child_c = (const float*)d_in[0];
    const float* child_h = (const float*)d_in[1];
    const float* hsum    = (const float*)d_in[2];
    const float* W_ih    = (const float*)d_in[3];
    const float* b_ih    = (const float*)d_in[4];
    const float* W_fh    = (const float*)d_in[5];
    const float* b_fh    = (const float*)d_in[6];
    const float* W_uh    = (const float*)d_in[7];
    const float* b_uh    = (const float*)d_in[8];
    const float* W_oh    = (const float*)d_in[9];
    const float* b_oh    = (const float*)d_in[10];
    float* out = (float*)d_out;

    cudaFuncSetAttribute(fgemm_kernel, cudaFuncAttributeMaxDynamicSharedMemorySize,
                         SMEM_BYTES);

    cvt_kernel<<<8704, 256>>>(child_h, W_fh);
    fgemm_kernel<<<NUM_CTAS, 512, SMEM_BYTES>>>(child_c, b_fh);
    final_kernel<<<1024, 128>>>(out, hsum, W_ih, b_ih, W_uh, b_uh, W_oh, b_oh);
}